// round 10
// baseline (speedup 1.0000x reference)
#include <cuda_runtime.h>
#include <math.h>
#include <stdint.h>

#define Bd 32
#define Td 512
#define Ed 256
#define Hd 256
#define Cd 20
#define G4 1024          // 4*H
#define HPAD 68          // padded k-quarter row for h_s (conflict-free 4-way)

// -------------------- f32x2 helpers (SASS FFMA2 only reachable via PTX) ---
__device__ __forceinline__ void ffma2(uint64_t& acc, uint64_t a, uint64_t b) {
    asm("fma.rn.f32x2 %0, %1, %2, %0;" : "+l"(acc) : "l"(a), "l"(b));
}
__device__ __forceinline__ uint64_t add2(uint64_t a, uint64_t b) {
    uint64_t d;
    asm("add.rn.f32x2 %0, %1, %2;" : "=l"(d) : "l"(a), "l"(b));
    return d;
}
__device__ __forceinline__ uint64_t pack2(float x) {   // {x, x}
    uint64_t d; uint32_t u = __float_as_uint(x);
    asm("mov.b64 %0, {%1, %1};" : "=l"(d) : "r"(u));
    return d;
}
__device__ __forceinline__ void unpack2(float& lo, float& hi, uint64_t v) {
    uint32_t l, h;
    asm("mov.b64 {%0, %1}, %2;" : "=r"(l), "=r"(h) : "l"(v));
    lo = __uint_as_float(l); hi = __uint_as_float(h);
}
__device__ __forceinline__ float sum2(uint64_t v) {
    float lo, hi; unpack2(lo, hi, v); return lo + hi;
}

// -------------------- fast transcendentals --------------------------------
__device__ __forceinline__ float tanh_fast(float x) {   // rel err ~2^-10.7
    float y;
    asm("tanh.approx.f32 %0, %1;" : "=f"(y) : "f"(x));
    return y;
}
__device__ __forceinline__ float sigmoid_fast(float x) { // 0.5*tanh(x/2)+0.5
    return fmaf(tanh_fast(0.5f * x), 0.5f, 0.5f);
}

// -------------------- cluster / DSMEM helpers -----------------------------
__device__ __forceinline__ uint32_t smem_u32(const void* p) {
    return (uint32_t)__cvta_generic_to_shared(p);
}
__device__ __forceinline__ uint32_t mapa_shared(uint32_t addr, uint32_t rank) {
    uint32_t r;
    asm("mapa.shared::cluster.u32 %0, %1, %2;" : "=r"(r) : "r"(addr), "r"(rank));
    return r;
}
__device__ __forceinline__ void st_cluster_f32(uint32_t addr, float v) {
    asm volatile("st.shared::cluster.f32 [%0], %1;" :: "r"(addr), "f"(v) : "memory");
}
#define CLUSTER_BAR() do { \
    asm volatile("barrier.cluster.arrive.aligned;" ::: "memory"); \
    asm volatile("barrier.cluster.wait.aligned;"   ::: "memory"); } while (0)

// -------------------- scratch (static device globals; no allocation) ------
__device__ float d_xp[(size_t)2 * Bd * Td * G4];      // [dir][b][t][g]   128 MB
__device__ float d_out_h[(size_t)2 * Td * Bd * Hd];   // [dir][t][b][j]    32 MB
__device__ float d_logits[(size_t)Bd * Td * Cd];      // [b][t][c]
__device__ float d_llh[Bd];

// -------------------- K1: xp[dir] = gather(emb) @ Wih^T + b ---------------
// M=B*T=16384, N=4H=1024, K=E=256. Tile 128x64, 256 threads, micro 8x4
// computed as 4 m-pairs x 4 n via FFMA2.
__global__ __launch_bounds__(256) void k1_proj(
    const int* __restrict__ x, const int* __restrict__ seq_len,
    const float* __restrict__ emb,
    const float* __restrict__ Wih_f, const float* __restrict__ b_f,
    const float* __restrict__ Wih_b, const float* __restrict__ b_b)
{
    const int dir = blockIdx.z;
    const float* W    = dir ? Wih_b : Wih_f;
    const float* bias = dir ? b_b   : b_f;

    __shared__ __align__(16) float As[32][132];   // [k][m]
    __shared__ __align__(16) float Bs[32][68];    // [k][n]
    __shared__ int toks[128];

    const int m0 = blockIdx.x * 128;
    const int n0 = blockIdx.y * 64;
    const int tid = threadIdx.x;

    if (tid < 128) {
        int m = m0 + tid;
        int b = m >> 9, t = m & 511;
        int tok;
        if (dir == 0) {
            tok = x[m];
        } else {
            int sl = seq_len[b];
            int tt = (t < sl) ? (sl - 1 - t) : t;   // reversed sequence
            tok = x[(b << 9) + tt];
        }
        toks[tid] = tok;
    }
    __syncthreads();

    const int tx = tid & 15;   // n micro-tile (4 cols)
    const int ty = tid >> 4;   // m micro-tile (8 rows = 4 pairs)

    uint64_t accv[4][4];       // [m-pair][n], f32x2 over (row 2p, row 2p+1)
#pragma unroll
    for (int p = 0; p < 4; ++p)
#pragma unroll
        for (int j = 0; j < 4; ++j) accv[p][j] = 0ull;

    for (int k0 = 0; k0 < Ed; k0 += 32) {
        // A tile: As[k][m] = emb[tok(m)][k0+k]
        {
            int rsub = tid >> 3;            // 0..31
            int kq   = (tid & 7) << 2;      // 0,4,...,28
#pragma unroll
            for (int p = 0; p < 4; ++p) {
                int row = p * 32 + rsub;
                const float4 v = *reinterpret_cast<const float4*>(
                    emb + (size_t)toks[row] * Ed + k0 + kq);
                As[kq + 0][row] = v.x; As[kq + 1][row] = v.y;
                As[kq + 2][row] = v.z; As[kq + 3][row] = v.w;
            }
        }
        // B tile: Bs[k][n] = W[(n0+n)*E + k0+k]
        {
            int nl = tid & 63;
            int kq = (tid >> 6) << 3;       // 0,8,16,24
            const float* wp = W + (size_t)(n0 + nl) * Ed + k0 + kq;
            const float4 v0 = *reinterpret_cast<const float4*>(wp);
            const float4 v1 = *reinterpret_cast<const float4*>(wp + 4);
            Bs[kq + 0][nl] = v0.x; Bs[kq + 1][nl] = v0.y;
            Bs[kq + 2][nl] = v0.z; Bs[kq + 3][nl] = v0.w;
            Bs[kq + 4][nl] = v1.x; Bs[kq + 5][nl] = v1.y;
            Bs[kq + 6][nl] = v1.z; Bs[kq + 7][nl] = v1.w;
        }
        __syncthreads();

#pragma unroll
        for (int kk = 0; kk < 32; ++kk) {
            // 8 A values = 4 packed m-pairs (16B-aligned: row 528B, 32B offset)
            const ulonglong2 aA = *reinterpret_cast<const ulonglong2*>(&As[kk][ty * 8]);
            const ulonglong2 aB = *reinterpret_cast<const ulonglong2*>(&As[kk][ty * 8 + 4]);
            const float4 bv = *reinterpret_cast<const float4*>(&Bs[kk][tx * 4]);
            const uint64_t bd0 = pack2(bv.x), bd1 = pack2(bv.y);
            const uint64_t bd2 = pack2(bv.z), bd3 = pack2(bv.w);
            ffma2(accv[0][0], aA.x, bd0); ffma2(accv[0][1], aA.x, bd1);
            ffma2(accv[0][2], aA.x, bd2); ffma2(accv[0][3], aA.x, bd3);
            ffma2(accv[1][0], aA.y, bd0); ffma2(accv[1][1], aA.y, bd1);
            ffma2(accv[1][2], aA.y, bd2); ffma2(accv[1][3], aA.y, bd3);
            ffma2(accv[2][0], aB.x, bd0); ffma2(accv[2][1], aB.x, bd1);
            ffma2(accv[2][2], aB.x, bd2); ffma2(accv[2][3], aB.x, bd3);
            ffma2(accv[3][0], aB.y, bd0); ffma2(accv[3][1], aB.y, bd1);
            ffma2(accv[3][2], aB.y, bd2); ffma2(accv[3][3], aB.y, bd3);
        }
        __syncthreads();
    }

    const float4 bv = *reinterpret_cast<const float4*>(bias + n0 + tx * 4);
#pragma unroll
    for (int p = 0; p < 4; ++p) {
        float lo[4], hi[4];
#pragma unroll
        for (int j = 0; j < 4; ++j) unpack2(lo[j], hi[j], accv[p][j]);
        int mA = m0 + ty * 8 + 2 * p;
        float4 oA, oB;
        oA.x = lo[0] + bv.x; oA.y = lo[1] + bv.y; oA.z = lo[2] + bv.z; oA.w = lo[3] + bv.w;
        oB.x = hi[0] + bv.x; oB.y = hi[1] + bv.y; oB.z = hi[2] + bv.z; oB.w = hi[3] + bv.w;
        *reinterpret_cast<float4*>(
            d_xp + ((size_t)dir * Bd * Td + mA) * G4 + n0 + tx * 4) = oA;
        *reinterpret_cast<float4*>(
            d_xp + ((size_t)dir * Bd * Td + mA + 1) * G4 + n0 + tx * 4) = oB;
    }
}

// -------------------- K2: LSTM scans, cluster-of-8 + DSMEM h exchange -----
// 128 CTAs = 16 clusters of 8. Cluster = (dir, batch-group of 4 batches);
// rank jg = blockIdx.x & 7 owns 32 hidden units (128 gate rows), weights
// register-stationary (64 packed u64/thread). h(t) is broadcast by each cell
// thread directly into all 8 cluster CTAs' h_s2[(t+1)&1] via
// st.shared::cluster (double-buffered); ONE barrier.cluster per step replaces
// the old L2 spin barrier + h store/reload round-trip (~5000 -> ~1900 cyc).
__global__ __launch_bounds__(256, 1) __cluster_dims__(8, 1, 1)
void k2_scan(const float* __restrict__ Whh_f, const float* __restrict__ Whh_b)
{
    const int dir = blockIdx.x >> 6;
    const int bg  = (blockIdx.x >> 3) & 7;
    const int jg  = blockIdx.x & 7;                  // == cluster rank
    const float* Whh = dir ? Whh_b : Whh_f;

    __shared__ __align__(16) float h_s2[2][16 * HPAD]; // double-buffered h
    __shared__ __align__(16) float g_s[4 * 128];       // [bl][r]
    __shared__ __align__(16) float c_s[128];

    const int tid  = threadIdx.x;
    const int lane = tid & 31;
    const int w    = tid >> 5;
    const int rlo  = lane & 7;
    const int kh   = lane >> 3;
    const int rp   = w * 8 + rlo;         // 0..63
    const int r0   = 2 * rp, r1 = r0 + 1; // same gate block (r0 even)
    const int gate = r0 >> 5;
    const int gidx0 = (gate << 8) + (jg << 5) + (r0 & 31);  // xp/Whh row index

    // ---- load weight slices into registers (one-time) ----
    uint64_t w0[32], w1[32];
    {
        const float* wr0 = Whh + (size_t)gidx0 * Hd + kh * 64;
        const float* wr1 = Whh + (size_t)(gidx0 + 1) * Hd + kh * 64;
#pragma unroll
        for (int i = 0; i < 16; ++i) {
            ulonglong2 v0 = *reinterpret_cast<const ulonglong2*>(wr0 + i * 4);
            ulonglong2 v1 = *reinterpret_cast<const ulonglong2*>(wr1 + i * 4);
            w0[2 * i] = v0.x; w0[2 * i + 1] = v0.y;
            w1[2 * i] = v1.x; w1[2 * i + 1] = v1.y;
        }
    }
    if (tid < 128) c_s[tid] = 0.f;

    const int b0 = bg * 4;
    float* out      = d_out_h + (size_t)dir * Td * Bd * Hd;
    const float* xp = d_xp    + (size_t)dir * Bd * Td * G4;

    // DSMEM destination offset for this thread's h value (cell threads only):
    // unit jhid = jg*32 + (tid&31), batch bl = tid>>5 ->
    // h_s2[.][ (bl*4 + (jhid>>6)) * HPAD + (jhid & 63) ]
    const int cell_bl = tid >> 5;          // valid for tid<128
    const int cell_j  = tid & 31;
    const int dst_off = (cell_bl * 4 + (jg >> 1)) * HPAD + ((jg & 1) << 5) + cell_j;
    const uint32_t hbuf0_u32 = smem_u32(&h_s2[0][0]);
    const uint32_t bufbytes  = 16 * HPAD * 4;

    __syncthreads();

    for (int t = 0; t < Td; ++t) {
        const float* hbuf = h_s2[t & 1];

        // xp for this step (only kh==0 lanes contribute); float2: adjacent cols
        float xpv0[4], xpv1[4];
        if (lane < 8) {
#pragma unroll
            for (int bl = 0; bl < 4; ++bl) {
                const float2 xv = *reinterpret_cast<const float2*>(
                    xp + ((size_t)(b0 + bl) * Td + t) * G4 + gidx0);
                xpv0[bl] = xv.x; xpv1[bl] = xv.y;
            }
        }

        uint64_t acc[2][4];
#pragma unroll
        for (int rr = 0; rr < 2; ++rr)
#pragma unroll
            for (int bl = 0; bl < 4; ++bl) acc[rr][bl] = 0ull;

        if (t > 0) {
            const ulonglong2* h2b[4];
#pragma unroll
            for (int bl = 0; bl < 4; ++bl)
                h2b[bl] = reinterpret_cast<const ulonglong2*>(
                    hbuf + (bl * 4 + kh) * HPAD);
#pragma unroll
            for (int ii = 0; ii < 16; ++ii) {
                const ulonglong2 hv0 = h2b[0][ii];
                const ulonglong2 hv1 = h2b[1][ii];
                const ulonglong2 hv2 = h2b[2][ii];
                const ulonglong2 hv3 = h2b[3][ii];
                const uint64_t wa = w0[2 * ii], wb = w0[2 * ii + 1];
                const uint64_t wc = w1[2 * ii], wd = w1[2 * ii + 1];
                ffma2(acc[0][0], hv0.x, wa); ffma2(acc[0][0], hv0.y, wb);
                ffma2(acc[1][0], hv0.x, wc); ffma2(acc[1][0], hv0.y, wd);
                ffma2(acc[0][1], hv1.x, wa); ffma2(acc[0][1], hv1.y, wb);
                ffma2(acc[1][1], hv1.x, wc); ffma2(acc[1][1], hv1.y, wd);
                ffma2(acc[0][2], hv2.x, wa); ffma2(acc[0][2], hv2.y, wb);
                ffma2(acc[1][2], hv2.x, wc); ffma2(acc[1][2], hv2.y, wd);
                ffma2(acc[0][3], hv3.x, wa); ffma2(acc[0][3], hv3.y, wb);
                ffma2(acc[1][3], hv3.x, wc); ffma2(acc[1][3], hv3.y, wd);
            }
        }

        // reduce across kh (lanes xor 8, 16) in packed f32x2, then finalize
#pragma unroll
        for (int rr = 0; rr < 2; ++rr)
#pragma unroll
            for (int bl = 0; bl < 4; ++bl) {
                uint64_t v = acc[rr][bl];
                v = add2(v, __shfl_xor_sync(0xffffffffu, v, 8));
                v = add2(v, __shfl_xor_sync(0xffffffffu, v, 16));
                acc[rr][bl] = v;
            }
        if (lane < 8) {
#pragma unroll
            for (int bl = 0; bl < 4; ++bl) {
                g_s[bl * 128 + r0] = xpv0[bl] + sum2(acc[0][bl]);
                g_s[bl * 128 + r1] = xpv1[bl] + sum2(acc[1][bl]);
            }
        }
        __syncthreads();

        if (tid < 128) {  // elementwise LSTM cell for (4 batches x 32 units)
            float* gb = g_s + cell_bl * 128;
            float gi = gb[cell_j], gf = gb[32 + cell_j];
            float gg = gb[64 + cell_j], go = gb[96 + cell_j];
            float i_ = sigmoid_fast(gi);
            float f_ = sigmoid_fast(gf);
            float o_ = sigmoid_fast(go);
            float c  = f_ * c_s[tid] + i_ * tanh_fast(gg);
            c_s[tid] = c;
            float h  = o_ * tanh_fast(c);
            // global copy for K3 (off critical path)
            out[((size_t)t * Bd + (b0 + cell_bl)) * Hd + (jg << 5) + cell_j] = h;
            // DSMEM broadcast into all 8 cluster CTAs' next-step buffer
            const uint32_t base = hbuf0_u32 + ((t & 1) ^ 1) * bufbytes + dst_off * 4;
#pragma unroll
            for (uint32_t r = 0; r < 8; ++r)
                st_cluster_f32(mapa_shared(base, r), h);
        }
        CLUSTER_BAR();   // release DSMEM stores; all CTAs step together
    }
}

// -------------------- K3: logits = log_softmax(outs @ W_fc^T) -------------
// One warp per (b,t). W_fc staged TRANSPOSED into dynamic smem: W_s[k][c]
// (conflict-free LDS across the 20 lanes). Masked (b,t) exit immediately.
__global__ __launch_bounds__(256) void k3_logits(
    const int* __restrict__ seq_len, const float* __restrict__ W_fc)
{
    extern __shared__ __align__(16) float dynsm[];
    float* W_s    = dynsm;                 // [512][20], 40960 B
    float* os_all = dynsm + 512 * Cd;      // [8][512],  16384 B

    const int tid = threadIdx.x;
    // stage W_fc transposed (coalesced read; one-time scatter to smem)
    for (int i = tid; i < Cd * 512; i += 256) {
        int c = i >> 9, k = i & 511;
        W_s[k * Cd + c] = W_fc[i];
    }
    __syncthreads();

    const int warp = tid >> 5, lane = tid & 31;
    const int idx = blockIdx.x * 8 + warp;           // 0..16383
    const int b = idx >> 9, t = idx & 511;
    const int sl = seq_len[b];
    if (t >= sl) return;                             // masked: logits unread
    const int tb = sl - 1 - t;                       // un-reverse index

    float* os = os_all + warp * 512;
    const float* of = d_out_h + ((size_t)t  * Bd + b) * Hd;
    const float* ob = d_out_h + (size_t)Td * Bd * Hd + ((size_t)tb * Bd + b) * Hd;
    for (int k = lane; k < 256; k += 32) {
        os[k]       = of[k];
        os[256 + k] = ob[k];
    }
    __syncwarp();

    float raw;
    if (lane < Cd) {
        float s0 = 0.f, s1 = 0.f, s2 = 0.f, s3 = 0.f;
#pragma unroll 4
        for (int k = 0; k < 512; k += 4) {
            const float4 ov = *reinterpret_cast<const float4*>(os + k);
            s0 += ov.x * W_s[(k + 0) * Cd + lane];
            s1 += ov.y * W_s[(k + 1) * Cd + lane];
            s2 += ov.z * W_s[(k + 2) * Cd + lane];
            s3 += ov.w * W_s[(k + 3) * Cd + lane];
        }
        raw = (s0 + s1) + (s2 + s3);
    } else {
        raw = -INFINITY;
    }
    float mx = raw;
#pragma unroll
    for (int o = 16; o; o >>= 1) mx = fmaxf(mx, __shfl_xor_sync(0xffffffffu, mx, o));
    float e = (lane < Cd) ? __expf(raw - mx) : 0.f;
    float sum = e;
#pragma unroll
    for (int o = 16; o; o >>= 1) sum += __shfl_xor_sync(0xffffffffu, sum, o);
    if (lane < Cd)
        d_logits[((size_t)b * Td + t) * Cd + lane] = raw - mx - __logf(sum);
}

// -------------------- K4: CRF score + forward algorithm, per batch --------
__global__ __launch_bounds__(32) void k4_crf(
    const int* __restrict__ seq_len, const int* __restrict__ y,
    const float* __restrict__ start_t, const float* __restrict__ end_t,
    const float* __restrict__ trans)
{
    __shared__ float tr_s[Cd * Cd];
    __shared__ float alpha_s[32];
    const int b = blockIdx.x, lane = threadIdx.x;
    for (int i = lane; i < Cd * Cd; i += 32) tr_s[i] = trans[i];
    __syncwarp();

    const int sl = seq_len[b];
    const int* yb = y + (size_t)b * Td;
    const float* lg = d_logits + (size_t)b * Td * Cd;

    // gold-path score terms for t = 1..sl-1 (distributed over lanes)
    float sc = 0.f;
    for (int t = 1 + lane; t < sl; t += 32)
        sc += tr_s[yb[t - 1] * Cd + yb[t]] + lg[(size_t)t * Cd + yb[t]];
#pragma unroll
    for (int o = 16; o; o >>= 1) sc += __shfl_xor_sync(0xffffffffu, sc, o);

    // forward algorithm: lane c holds alpha[c]
    const int cl = (lane < Cd) ? lane : 0;
    float alpha = start_t[cl] + lg[cl];
    for (int t = 1; t < sl; ++t) {
        alpha_s[lane] = alpha;
        __syncwarp();
        float mx = -INFINITY;
#pragma unroll
        for (int c = 0; c < Cd; ++c) mx = fmaxf(mx, alpha_s[c] + tr_s[c * Cd + cl]);
        float s = 0.f;
#pragma unroll
        for (int c = 0; c < Cd; ++c) s += __expf(alpha_s[c] + tr_s[c * Cd + cl] - mx);
        alpha = mx + __logf(s) + lg[(size_t)t * Cd + cl];
        __syncwarp();
    }
    float v = (lane < Cd) ? (alpha + end_t[lane]) : -INFINITY;
    float mx = v;
#pragma unroll
    for (int o = 16; o; o >>= 1) mx = fmaxf(mx, __shfl_xor_sync(0xffffffffu, mx, o));
    float e = (lane < Cd) ? __expf(v - mx) : 0.f;
    float sum = e;
#pragma unroll
    for (int o = 16; o; o >>= 1) sum += __shfl_xor_sync(0xffffffffu, sum, o);

    if (lane == 0) {
        float logZ  = mx + __logf(sum);
        float first = start_t[yb[0]] + lg[yb[0]];
        float score = first + sc + end_t[yb[sl - 1]];
        d_llh[b] = score - logZ;
    }
}

// -------------------- K5: final reduction --------------------------------
__global__ void k5_reduce(float* __restrict__ out) {
    const int lane = threadIdx.x;
    float v = d_llh[lane];
#pragma unroll
    for (int o = 16; o; o >>= 1) v += __shfl_xor_sync(0xffffffffu, v, o);
    if (lane == 0) out[0] = -v;
}

// -------------------- launch ---------------------------------------------
extern "C" void kernel_launch(void* const* d_in, const int* in_sizes, int n_in,
                              void* d_out, int out_size)
{
    const int*   x       = (const int*)  d_in[0];
    const int*   seq_len = (const int*)  d_in[1];
    const int*   y       = (const int*)  d_in[2];
    // d_in[3] = mask  (unused: derived exactly from seq_len)
    const float* emb     = (const float*)d_in[4];
    const float* Wih_f   = (const float*)d_in[5];
    const float* Whh_f   = (const float*)d_in[6];
    const float* b_f     = (const float*)d_in[7];
    const float* Wih_b   = (const float*)d_in[8];
    const float* Whh_b   = (const float*)d_in[9];
    const float* b_b     = (const float*)d_in[10];
    const float* W_fc    = (const float*)d_in[11];
    const float* start_t = (const float*)d_in[12];
    const float* end_t   = (const float*)d_in[13];
    const float* trans   = (const float*)d_in[14];

    const int k3_smem = (512 * Cd + 8 * 512) * (int)sizeof(float);  // 57344 B
    static int k3_attr_set = 0;
    if (!k3_attr_set) {
        cudaFuncSetAttribute(k3_logits,
                             cudaFuncAttributeMaxDynamicSharedMemorySize, k3_smem);
        k3_attr_set = 1;
    }

    dim3 g1(Bd * Td / 128, G4 / 64, 2);
    k1_proj<<<g1, 256>>>(x, seq_len, emb, Wih_f, b_f, Wih_b, b_b);
    k2_scan<<<128, 256>>>(Whh_f, Whh_b);
    k3_logits<<<Bd * Td / 8, 256, k3_smem>>>(seq_len, W_fc);
    k4_crf<<<Bd, 32>>>(seq_len, y, start_t, end_t, trans);
    k5_reduce<<<1, 32>>>((float*)d_out);
}

// round 14
// speedup vs baseline: 1.3270x; 1.3270x over previous
#include <cuda_runtime.h>
#include <math.h>
#include <stdint.h>

#define Bd 32
#define Td 512
#define Ed 256
#define Hd 256
#define Cd 20
#define G4 1024          // 4*H
#define HPAD 68          // padded k-quarter row for h_s (conflict-free 4-way)

// -------------------- f32x2 helpers (SASS FFMA2 only reachable via PTX) ---
__device__ __forceinline__ void ffma2(uint64_t& acc, uint64_t a, uint64_t b) {
    asm("fma.rn.f32x2 %0, %1, %2, %0;" : "+l"(acc) : "l"(a), "l"(b));
}
__device__ __forceinline__ uint64_t add2(uint64_t a, uint64_t b) {
    uint64_t d;
    asm("add.rn.f32x2 %0, %1, %2;" : "=l"(d) : "l"(a), "l"(b));
    return d;
}
__device__ __forceinline__ uint64_t pack2(float x) {   // {x, x}
    uint64_t d; uint32_t u = __float_as_uint(x);
    asm("mov.b64 %0, {%1, %1};" : "=l"(d) : "r"(u));
    return d;
}
__device__ __forceinline__ void unpack2(float& lo, float& hi, uint64_t v) {
    uint32_t l, h;
    asm("mov.b64 {%0, %1}, %2;" : "=r"(l), "=r"(h) : "l"(v));
    lo = __uint_as_float(l); hi = __uint_as_float(h);
}
__device__ __forceinline__ float sum2(uint64_t v) {
    float lo, hi; unpack2(lo, hi, v); return lo + hi;
}

// -------------------- fast transcendentals --------------------------------
__device__ __forceinline__ float tanh_fast(float x) {   // rel err ~2^-10.7
    float y;
    asm("tanh.approx.f32 %0, %1;" : "=f"(y) : "f"(x));
    return y;
}
__device__ __forceinline__ float sigmoid_fast(float x) { // 0.5*tanh(x/2)+0.5
    return fmaf(tanh_fast(0.5f * x), 0.5f, 0.5f);
}

// -------------------- scratch (static device globals; no allocation) ------
__device__ float d_xp[(size_t)2 * Bd * Td * G4];      // [dir][b][t][g]   128 MB
__device__ float d_out_h[(size_t)2 * Td * Bd * Hd];   // [dir][t][b][j]    32 MB
__device__ float d_logits[(size_t)Bd * Td * Cd];      // [b][t][c]
__device__ float d_llh[Bd];
__device__ unsigned d_bar[16];                        // [dir*8 + batch_group]

// -------------------- K0: reset inter-CTA barrier counters ----------------
__global__ void k0_init() {
    if (threadIdx.x < 16) d_bar[threadIdx.x] = 0u;
}

// -------------------- K1: xp[dir] = gather(emb) @ Wih^T + b ---------------
// M=B*T=16384, N=4H=1024, K=E=256. Tile 128x64, 256 threads, micro 8x4
// computed as 4 m-pairs x 4 n via FFMA2.
__global__ __launch_bounds__(256) void k1_proj(
    const int* __restrict__ x, const int* __restrict__ seq_len,
    const float* __restrict__ emb,
    const float* __restrict__ Wih_f, const float* __restrict__ b_f,
    const float* __restrict__ Wih_b, const float* __restrict__ b_b)
{
    const int dir = blockIdx.z;
    const float* W    = dir ? Wih_b : Wih_f;
    const float* bias = dir ? b_b   : b_f;

    __shared__ __align__(16) float As[32][132];   // [k][m]
    __shared__ __align__(16) float Bs[32][68];    // [k][n]
    __shared__ int toks[128];

    const int m0 = blockIdx.x * 128;
    const int n0 = blockIdx.y * 64;
    const int tid = threadIdx.x;

    if (tid < 128) {
        int m = m0 + tid;
        int b = m >> 9, t = m & 511;
        int tok;
        if (dir == 0) {
            tok = x[m];
        } else {
            int sl = seq_len[b];
            int tt = (t < sl) ? (sl - 1 - t) : t;   // reversed sequence
            tok = x[(b << 9) + tt];
        }
        toks[tid] = tok;
    }
    __syncthreads();

    const int tx = tid & 15;   // n micro-tile (4 cols)
    const int ty = tid >> 4;   // m micro-tile (8 rows = 4 pairs)

    uint64_t accv[4][4];       // [m-pair][n], f32x2 over (row 2p, row 2p+1)
#pragma unroll
    for (int p = 0; p < 4; ++p)
#pragma unroll
        for (int j = 0; j < 4; ++j) accv[p][j] = 0ull;

    for (int k0 = 0; k0 < Ed; k0 += 32) {
        // A tile: As[k][m] = emb[tok(m)][k0+k]
        {
            int rsub = tid >> 3;            // 0..31
            int kq   = (tid & 7) << 2;      // 0,4,...,28
#pragma unroll
            for (int p = 0; p < 4; ++p) {
                int row = p * 32 + rsub;
                const float4 v = *reinterpret_cast<const float4*>(
                    emb + (size_t)toks[row] * Ed + k0 + kq);
                As[kq + 0][row] = v.x; As[kq + 1][row] = v.y;
                As[kq + 2][row] = v.z; As[kq + 3][row] = v.w;
            }
        }
        // B tile: Bs[k][n] = W[(n0+n)*E + k0+k]
        {
            int nl = tid & 63;
            int kq = (tid >> 6) << 3;       // 0,8,16,24
            const float* wp = W + (size_t)(n0 + nl) * Ed + k0 + kq;
            const float4 v0 = *reinterpret_cast<const float4*>(wp);
            const float4 v1 = *reinterpret_cast<const float4*>(wp + 4);
            Bs[kq + 0][nl] = v0.x; Bs[kq + 1][nl] = v0.y;
            Bs[kq + 2][nl] = v0.z; Bs[kq + 3][nl] = v0.w;
            Bs[kq + 4][nl] = v1.x; Bs[kq + 5][nl] = v1.y;
            Bs[kq + 6][nl] = v1.z; Bs[kq + 7][nl] = v1.w;
        }
        __syncthreads();

#pragma unroll
        for (int kk = 0; kk < 32; ++kk) {
            // 8 A values = 4 packed m-pairs (16B-aligned: row 528B, 32B offset)
            const ulonglong2 aA = *reinterpret_cast<const ulonglong2*>(&As[kk][ty * 8]);
            const ulonglong2 aB = *reinterpret_cast<const ulonglong2*>(&As[kk][ty * 8 + 4]);
            const float4 bv = *reinterpret_cast<const float4*>(&Bs[kk][tx * 4]);
            const uint64_t bd0 = pack2(bv.x), bd1 = pack2(bv.y);
            const uint64_t bd2 = pack2(bv.z), bd3 = pack2(bv.w);
            ffma2(accv[0][0], aA.x, bd0); ffma2(accv[0][1], aA.x, bd1);
            ffma2(accv[0][2], aA.x, bd2); ffma2(accv[0][3], aA.x, bd3);
            ffma2(accv[1][0], aA.y, bd0); ffma2(accv[1][1], aA.y, bd1);
            ffma2(accv[1][2], aA.y, bd2); ffma2(accv[1][3], aA.y, bd3);
            ffma2(accv[2][0], aB.x, bd0); ffma2(accv[2][1], aB.x, bd1);
            ffma2(accv[2][2], aB.x, bd2); ffma2(accv[2][3], aB.x, bd3);
            ffma2(accv[3][0], aB.y, bd0); ffma2(accv[3][1], aB.y, bd1);
            ffma2(accv[3][2], aB.y, bd2); ffma2(accv[3][3], aB.y, bd3);
        }
        __syncthreads();
    }

    const float4 bv = *reinterpret_cast<const float4*>(bias + n0 + tx * 4);
#pragma unroll
    for (int p = 0; p < 4; ++p) {
        float lo[4], hi[4];
#pragma unroll
        for (int j = 0; j < 4; ++j) unpack2(lo[j], hi[j], accv[p][j]);
        int mA = m0 + ty * 8 + 2 * p;
        float4 oA, oB;
        oA.x = lo[0] + bv.x; oA.y = lo[1] + bv.y; oA.z = lo[2] + bv.z; oA.w = lo[3] + bv.w;
        oB.x = hi[0] + bv.x; oB.y = hi[1] + bv.y; oB.z = hi[2] + bv.z; oB.w = hi[3] + bv.w;
        *reinterpret_cast<float4*>(
            d_xp + ((size_t)dir * Bd * Td + mA) * G4 + n0 + tx * 4) = oA;
        *reinterpret_cast<float4*>(
            d_xp + ((size_t)dir * Bd * Td + mA + 1) * G4 + n0 + tx * 4) = oB;
    }
}

// -------------------- K2: LSTM scans, REGISTER-stationary weights ---------
// (Measured-good spin-barrier protocol; the cluster/DSMEM variant regressed
// 1833->2329 and was reverted.) 128 CTAs = 2 dirs x 8 batch-groups x 8
// j-groups; weights in registers; h staged to padded smem; inter-CTA step
// barrier via red.release.gpu + ld.acquire.gpu spin.
__global__ __launch_bounds__(256, 1) void k2_scan(
    const float* __restrict__ Whh_f, const float* __restrict__ Whh_b)
{
    const int dir = blockIdx.x >> 6;
    const int bg  = (blockIdx.x >> 3) & 7;
    const int jg  = blockIdx.x & 7;
    const float* Whh = dir ? Whh_b : Whh_f;

    __shared__ __align__(16) float h_s[16 * HPAD];   // [bl*4 + kh][68]
    __shared__ __align__(16) float g_s[4 * 128];     // [bl][r]  (r = gate*32 + unit)
    __shared__ __align__(16) float c_s[128];

    const int tid  = threadIdx.x;
    const int lane = tid & 31;
    const int w    = tid >> 5;
    const int rlo  = lane & 7;
    const int kh   = lane >> 3;
    const int rp   = w * 8 + rlo;         // 0..63
    const int r0   = 2 * rp, r1 = r0 + 1; // same gate block (r0 even)
    const int gate = r0 >> 5;
    const int gidx0 = (gate << 8) + (jg << 5) + (r0 & 31);  // xp/Whh row index

    // ---- load weight slices into registers (one-time) ----
    uint64_t w0[32], w1[32];
    {
        const float* wr0 = Whh + (size_t)gidx0 * Hd + kh * 64;
        const float* wr1 = Whh + (size_t)(gidx0 + 1) * Hd + kh * 64;
#pragma unroll
        for (int i = 0; i < 16; ++i) {
            ulonglong2 v0 = *reinterpret_cast<const ulonglong2*>(wr0 + i * 4);
            ulonglong2 v1 = *reinterpret_cast<const ulonglong2*>(wr1 + i * 4);
            w0[2 * i] = v0.x; w0[2 * i + 1] = v0.y;
            w1[2 * i] = v1.x; w1[2 * i + 1] = v1.y;
        }
    }
    if (tid < 128) c_s[tid] = 0.f;

    const int b0 = bg * 4;
    unsigned* bar = d_bar + dir * 8 + bg;
    float* out      = d_out_h + (size_t)dir * Td * Bd * Hd;
    const float* xp = d_xp    + (size_t)dir * Bd * Td * G4;

    // h_s base pointers for this thread's k-quarter, per local batch
    const ulonglong2* h2b[4];
#pragma unroll
    for (int bl = 0; bl < 4; ++bl)
        h2b[bl] = reinterpret_cast<const ulonglong2*>(h_s + (bl * 4 + kh) * HPAD);

    // staging indices (each thread moves one float4 of h into padded h_s)
    const int sidx4 = tid * 4;
    const int s_bl = sidx4 >> 8, s_k = sidx4 & 255;
    float* s_dst = h_s + ((s_bl << 2) + (s_k >> 6)) * HPAD + (s_k & 63);
    __syncthreads();

    for (int t = 0; t < Td; ++t) {
        if (t > 0) {  // stage h(t-1) for our 4 batches: 1024 floats, padded
            const float4 v = reinterpret_cast<const float4*>(
                out + ((size_t)(t - 1) * Bd + b0) * Hd)[tid];
            *reinterpret_cast<float4*>(s_dst) = v;
        }

        // xp for this step (only kh==0 lanes write g); float2: adjacent cols
        float xpv0[4], xpv1[4];
        if (lane < 8) {
#pragma unroll
            for (int bl = 0; bl < 4; ++bl) {
                const float2 xv = *reinterpret_cast<const float2*>(
                    xp + ((size_t)(b0 + bl) * Td + t) * G4 + gidx0);
                xpv0[bl] = xv.x; xpv1[bl] = xv.y;
            }
        }
        __syncthreads();

        uint64_t acc[2][4];
#pragma unroll
        for (int rr = 0; rr < 2; ++rr)
#pragma unroll
            for (int bl = 0; bl < 4; ++bl) acc[rr][bl] = 0ull;

        if (t > 0) {
#pragma unroll
            for (int ii = 0; ii < 16; ++ii) {
                const ulonglong2 hv0 = h2b[0][ii];
                const ulonglong2 hv1 = h2b[1][ii];
                const ulonglong2 hv2 = h2b[2][ii];
                const ulonglong2 hv3 = h2b[3][ii];
                const uint64_t wa = w0[2 * ii], wb = w0[2 * ii + 1];
                const uint64_t wc = w1[2 * ii], wd = w1[2 * ii + 1];
                ffma2(acc[0][0], hv0.x, wa); ffma2(acc[0][0], hv0.y, wb);
                ffma2(acc[1][0], hv0.x, wc); ffma2(acc[1][0], hv0.y, wd);
                ffma2(acc[0][1], hv1.x, wa); ffma2(acc[0][1], hv1.y, wb);
                ffma2(acc[1][1], hv1.x, wc); ffma2(acc[1][1], hv1.y, wd);
                ffma2(acc[0][2], hv2.x, wa); ffma2(acc[0][2], hv2.y, wb);
                ffma2(acc[1][2], hv2.x, wc); ffma2(acc[1][2], hv2.y, wd);
                ffma2(acc[0][3], hv3.x, wa); ffma2(acc[0][3], hv3.y, wb);
                ffma2(acc[1][3], hv3.x, wc); ffma2(acc[1][3], hv3.y, wd);
            }
        }

        // reduce across kh (lanes xor 8, 16) in packed f32x2, then finalize
#pragma unroll
        for (int rr = 0; rr < 2; ++rr)
#pragma unroll
            for (int bl = 0; bl < 4; ++bl) {
                uint64_t v = acc[rr][bl];
                v = add2(v, __shfl_xor_sync(0xffffffffu, v, 8));
                v = add2(v, __shfl_xor_sync(0xffffffffu, v, 16));
                acc[rr][bl] = v;
            }
        if (lane < 8) {
#pragma unroll
            for (int bl = 0; bl < 4; ++bl) {
                g_s[bl * 128 + r0] = xpv0[bl] + sum2(acc[0][bl]);
                g_s[bl * 128 + r1] = xpv1[bl] + sum2(acc[1][bl]);
            }
        }
        __syncthreads();

        if (tid < 128) {  // elementwise LSTM cell for (4 batches x 32 units)
            int bl = tid >> 5, j = tid & 31;
            float* gb = g_s + bl * 128;
            float gi = gb[j], gf = gb[32 + j], gg = gb[64 + j], go = gb[96 + j];
            float i_ = sigmoid_fast(gi);
            float f_ = sigmoid_fast(gf);
            float o_ = sigmoid_fast(go);
            float c  = f_ * c_s[tid] + i_ * tanh_fast(gg);
            c_s[tid] = c;
            float h  = o_ * tanh_fast(c);
            out[((size_t)t * Bd + (b0 + bl)) * Hd + (jg << 5) + j] = h;
        }
        __syncthreads();
        if (tid == 0) {  // inter-CTA barrier among the 8 CTAs of (dir,bg)
            // release: orders this CTA's h stores before the counter bump
            asm volatile("red.release.gpu.add.u32 [%0], %1;"
                         :: "l"(bar), "r"(1u) : "memory");
            const unsigned target = 8u * (unsigned)(t + 1);
            unsigned v;
            do {
                asm volatile("ld.acquire.gpu.u32 %0, [%1];"
                             : "=r"(v) : "l"(bar) : "memory");
            } while (v < target);
        }
        __syncthreads();   // broadcasts tid0's acquire to the whole CTA
    }
}

// -------------------- K3: logits = log_softmax(outs @ W_fc^T) -------------
// One warp per (b,t). W_fc staged TRANSPOSED into dynamic smem: W_s[k][c]
// (conflict-free LDS across the 20 lanes). Masked (b,t) exit immediately.
__global__ __launch_bounds__(256) void k3_logits(
    const int* __restrict__ seq_len, const float* __restrict__ W_fc)
{
    extern __shared__ __align__(16) float dynsm[];
    float* W_s    = dynsm;                 // [512][20], 40960 B
    float* os_all = dynsm + 512 * Cd;      // [8][512],  16384 B

    const int tid = threadIdx.x;
    // stage W_fc transposed (coalesced read; one-time scatter to smem)
    for (int i = tid; i < Cd * 512; i += 256) {
        int c = i >> 9, k = i & 511;
        W_s[k * Cd + c] = W_fc[i];
    }
    __syncthreads();

    const int warp = tid >> 5, lane = tid & 31;
    const int idx = blockIdx.x * 8 + warp;           // 0..16383
    const int b = idx >> 9, t = idx & 511;
    const int sl = seq_len[b];
    if (t >= sl) return;                             // masked: logits unread
    const int tb = sl - 1 - t;                       // un-reverse index

    float* os = os_all + warp * 512;
    const float* of = d_out_h + ((size_t)t  * Bd + b) * Hd;
    const float* ob = d_out_h + (size_t)Td * Bd * Hd + ((size_t)tb * Bd + b) * Hd;
    for (int k = lane; k < 256; k += 32) {
        os[k]       = of[k];
        os[256 + k] = ob[k];
    }
    __syncwarp();

    float raw;
    if (lane < Cd) {
        float s0 = 0.f, s1 = 0.f, s2 = 0.f, s3 = 0.f;
#pragma unroll 4
        for (int k = 0; k < 512; k += 4) {
            const float4 ov = *reinterpret_cast<const float4*>(os + k);
            s0 += ov.x * W_s[(k + 0) * Cd + lane];
            s1 += ov.y * W_s[(k + 1) * Cd + lane];
            s2 += ov.z * W_s[(k + 2) * Cd + lane];
            s3 += ov.w * W_s[(k + 3) * Cd + lane];
        }
        raw = (s0 + s1) + (s2 + s3);
    } else {
        raw = -INFINITY;
    }
    float mx = raw;
#pragma unroll
    for (int o = 16; o; o >>= 1) mx = fmaxf(mx, __shfl_xor_sync(0xffffffffu, mx, o));
    float e = (lane < Cd) ? __expf(raw - mx) : 0.f;
    float sum = e;
#pragma unroll
    for (int o = 16; o; o >>= 1) sum += __shfl_xor_sync(0xffffffffu, sum, o);
    if (lane < Cd)
        d_logits[((size_t)b * Td + t) * Cd + lane] = raw - mx - __logf(sum);
}

// -------------------- K4: CRF score + SCALED LINEAR-DOMAIN forward --------
// Per batch, one warp. Instead of per-step logsumexp (20 serial __expf + max
// chains, measured 650cyc/step, 170us), keep p_d ~ exp(alpha_d - logscale):
// per step a 20x20 linear matvec with E=exp(trans) held in registers, ONE
// __expf (emit) per lane, emit prefetched one step ahead (hides L2 latency),
// warp-max renormalization every 8 steps. Underflowed components (<1e-38
// relative) are refilled by state mixing next step; error << 1e-3 tolerance.
__global__ __launch_bounds__(32) void k4_crf(
    const int* __restrict__ seq_len, const int* __restrict__ y,
    const float* __restrict__ start_t, const float* __restrict__ end_t,
    const float* __restrict__ trans)
{
    __shared__ float tr_s[Cd * Cd];
    __shared__ float p_s[32];
    const int b = blockIdx.x, lane = threadIdx.x;
    for (int i = lane; i < Cd * Cd; i += 32) tr_s[i] = trans[i];
    __syncwarp();

    const int sl = seq_len[b];
    const int* yb = y + (size_t)b * Td;
    const float* lg = d_logits + (size_t)b * Td * Cd;

    // gold-path score terms for t = 1..sl-1 (distributed over lanes)
    float sc = 0.f;
    for (int t = 1 + lane; t < sl; t += 32)
        sc += tr_s[yb[t - 1] * Cd + yb[t]] + lg[(size_t)t * Cd + yb[t]];
#pragma unroll
    for (int o = 16; o; o >>= 1) sc += __shfl_xor_sync(0xffffffffu, sc, o);

    const int cl = (lane < Cd) ? lane : 0;

    // E[c] = exp(trans[c][cl]), loop-invariant, in registers
    float E[Cd];
#pragma unroll
    for (int c = 0; c < Cd; ++c) E[c] = __expf(tr_s[c * Cd + cl]);

    // init: alpha0 = start + lg[0]; p = exp(alpha0 - m0); logscale = m0
    float a0 = (lane < Cd) ? (start_t[lane] + lg[lane]) : -INFINITY;
    float m0 = a0;
#pragma unroll
    for (int o = 16; o; o >>= 1) m0 = fmaxf(m0, __shfl_xor_sync(0xffffffffu, m0, o));
    float p = (lane < Cd) ? __expf(a0 - m0) : 0.f;
    float logscale = m0;

    float em_next = (sl > 1) ? lg[(size_t)1 * Cd + cl] : 0.f;  // prefetch t=1

    for (int t = 1; t < sl; ++t) {
        p_s[lane] = p;
        const float em = em_next;
        __syncwarp();
        if (t + 1 < sl) em_next = lg[(size_t)(t + 1) * Cd + cl];  // prefetch

        float q0 = 0.f, q1 = 0.f, q2 = 0.f, q3 = 0.f;
#pragma unroll
        for (int c = 0; c < Cd; c += 4) {
            q0 = fmaf(p_s[c + 0], E[c + 0], q0);
            q1 = fmaf(p_s[c + 1], E[c + 1], q1);
            q2 = fmaf(p_s[c + 2], E[c + 2], q2);
            q3 = fmaf(p_s[c + 3], E[c + 3], q3);
        }
        const float q = (q0 + q1) + (q2 + q3);
        p = (lane < Cd) ? q * __expf(em) : 0.f;

        if ((t & 7) == 7) {   // renormalize: p <= 1, logscale absorbs max
            float m = p;
#pragma unroll
            for (int o = 16; o; o >>= 1)
                m = fmaxf(m, __shfl_xor_sync(0xffffffffu, m, o));
            p *= __frcp_rn(m);
            logscale += __logf(m);
        }
        __syncwarp();   // protect next iteration's p_s write vs this read
    }

    float v = (lane < Cd) ? p * __expf(end_t[lane]) : 0.f;
    float sum = v;
#pragma unroll
    for (int o = 16; o; o >>= 1) sum += __shfl_xor_sync(0xffffffffu, sum, o);

    if (lane == 0) {
        float logZ  = logscale + __logf(sum);
        float first = start_t[yb[0]] + lg[yb[0]];
        float score = first + sc + end_t[yb[sl - 1]];
        d_llh[b] = score - logZ;
    }
}

// -------------------- K5: final reduction --------------------------------
__global__ void k5_reduce(float* __restrict__ out) {
    const int lane = threadIdx.x;
    float v = d_llh[lane];
#pragma unroll
    for (int o = 16; o; o >>= 1) v += __shfl_xor_sync(0xffffffffu, v, o);
    if (lane == 0) out[0] = -v;
}

// -------------------- launch ---------------------------------------------
extern "C" void kernel_launch(void* const* d_in, const int* in_sizes, int n_in,
                              void* d_out, int out_size)
{
    const int*   x       = (const int*)  d_in[0];
    const int*   seq_len = (const int*)  d_in[1];
    const int*   y       = (const int*)  d_in[2];
    // d_in[3] = mask  (unused: derived exactly from seq_len)
    const float* emb     = (const float*)d_in[4];
    const float* Wih_f   = (const float*)d_in[5];
    const float* Whh_f   = (const float*)d_in[6];
    const float* b_f     = (const float*)d_in[7];
    const float* Wih_b   = (const float*)d_in[8];
    const float* Whh_b   = (const float*)d_in[9];
    const float* b_b     = (const float*)d_in[10];
    const float* W_fc    = (const float*)d_in[11];
    const float* start_t = (const float*)d_in[12];
    const float* end_t   = (const float*)d_in[13];
    const float* trans   = (const float*)d_in[14];

    const int k3_smem = (512 * Cd + 8 * 512) * (int)sizeof(float);  // 57344 B
    static int k3_attr_set = 0;
    if (!k3_attr_set) {
        cudaFuncSetAttribute(k3_logits,
                             cudaFuncAttributeMaxDynamicSharedMemorySize, k3_smem);
        k3_attr_set = 1;
    }

    k0_init<<<1, 32>>>();
    dim3 g1(Bd * Td / 128, G4 / 64, 2);
    k1_proj<<<g1, 256>>>(x, seq_len, emb, Wih_f, b_f, Wih_b, b_b);
    k2_scan<<<128, 256>>>(Whh_f, Whh_b);
    k3_logits<<<Bd * Td / 8, 256, k3_smem>>>(seq_len, W_fc);
    k4_crf<<<Bd, 32>>>(seq_len, y, start_t, end_t, trans);
    k5_reduce<<<1, 32>>>((float*)d_out);
}